// round 1
// baseline (speedup 1.0000x reference)
#include <cuda_runtime.h>
#include <cuda_fp16.h>
#include <cstdint>

// Triplet loss: loss = mean(relu(||(a-p)W||^2 - ||(a-n)W||^2 + 0.2))
// (bias b cancels in the embedding differences)

#define ALPHA_C   0.2f
#define BTOT      8192
#define KDIM      2304
#define NDIM      128
#define ROWS_CTA  64
#define KC        64
#define KP        72          // padded K in smem (halves): conflict-free ldmatrix, 144B rows (16B aligned)
#define NCHUNK    (KDIM / KC) // 36

__device__ __half g_Wh[NDIM * KDIM];   // W transposed to [n][k], fp16
__device__ float  g_row_loss[BTOT];

// ---------------------------------------------------------------------------
__global__ void convW_kernel(const float* __restrict__ W) {
    int gid = blockIdx.x * blockDim.x + threadIdx.x;
    if (gid < NDIM * KDIM) {
        int n = gid / KDIM;
        int k = gid - n * KDIM;
        g_Wh[gid] = __float2half(W[(long)k * NDIM + n]);
    }
}

// ---------------------------------------------------------------------------
#define LDSM4(r0, r1, r2, r3, addr)                                          \
    asm volatile("ldmatrix.sync.aligned.m8n8.x4.shared.b16 {%0,%1,%2,%3}, [%4];" \
                 : "=r"(r0), "=r"(r1), "=r"(r2), "=r"(r3) : "r"(addr))

#define MMA16816(c0, c1, c2, c3, a0, a1, a2, a3, b0, b1)                     \
    asm volatile("mma.sync.aligned.m16n8k16.row.col.f32.f16.f16.f32 "        \
                 "{%0,%1,%2,%3}, {%4,%5,%6,%7}, {%8,%9}, {%0,%1,%2,%3};"     \
                 : "+f"(c0), "+f"(c1), "+f"(c2), "+f"(c3)                    \
                 : "r"(a0), "r"(a1), "r"(a2), "r"(a3), "r"(b0), "r"(b1))

__global__ void __launch_bounds__(256, 1)
triplet_main_kernel(const float* __restrict__ A,
                    const float* __restrict__ P,
                    const float* __restrict__ Ng) {
    __shared__ __align__(16) __half sdp[ROWS_CTA * KP];
    __shared__ __align__(16) __half sdn[ROWS_CTA * KP];
    __shared__ __align__(16) __half sW[NDIM * KP];
    __shared__ float sD[2][ROWS_CTA];

    const int tid  = threadIdx.x;
    const int warp = tid >> 5;
    const int lane = tid & 31;
    const int row0 = blockIdx.x * ROWS_CTA;

    // staging registers (prefetch of next K-chunk)
    float4 ra[4], rp[4], rn[4];
    int4   rw[4];

    // accumulators: 16 n-tiles (n8) x 4 f32
    float acc[16][4];
#pragma unroll
    for (int i = 0; i < 16; i++)
#pragma unroll
        for (int j = 0; j < 4; j++) acc[i][j] = 0.f;

    // --- per-lane ldmatrix address components (constant over loop) ---
    const int m0 = (warp & 3) * 16;                 // warp's 16-row slice
    const __half* atile = (warp < 4) ? sdp : sdn;   // warps 0-3: dp, 4-7: dn
    const uint32_t a_base = (uint32_t)__cvta_generic_to_shared(atile);
    const uint32_t w_base = (uint32_t)__cvta_generic_to_shared(sW);
    const int a_row  = m0 + (lane & 15);
    const int a_kadd = (lane >> 4) * 8;
    const int b_nrow = (lane & 7) + ((lane >> 4) * 8);
    const int b_kadd = ((lane >> 3) & 1) * 8;

    auto loadChunk = [&](int k0) {
#pragma unroll
        for (int it = 0; it < 4; it++) {
            int idx = it * 256 + tid;
            int r = idx >> 4, c4 = idx & 15;
            long off = (long)(row0 + r) * KDIM + k0 + c4 * 4;
            ra[it] = *(const float4*)(A + off);
            rp[it] = *(const float4*)(P + off);
            rn[it] = *(const float4*)(Ng + off);
        }
#pragma unroll
        for (int it = 0; it < 4; it++) {
            int idx = it * 256 + tid;
            int n = idx >> 3, c8 = idx & 7;
            rw[it] = *(const int4*)((const __half*)g_Wh + (long)n * KDIM + k0 + c8 * 8);
        }
    };

    auto storeChunk = [&]() {
#pragma unroll
        for (int it = 0; it < 4; it++) {
            int idx = it * 256 + tid;
            int r = idx >> 4, c4 = idx & 15;
            __half2 p01 = __floats2half2_rn(ra[it].x - rp[it].x, ra[it].y - rp[it].y);
            __half2 p23 = __floats2half2_rn(ra[it].z - rp[it].z, ra[it].w - rp[it].w);
            __half2 q01 = __floats2half2_rn(ra[it].x - rn[it].x, ra[it].y - rn[it].y);
            __half2 q23 = __floats2half2_rn(ra[it].z - rn[it].z, ra[it].w - rn[it].w);
            __half2* dp = (__half2*)(sdp + r * KP + c4 * 4);
            dp[0] = p01; dp[1] = p23;
            __half2* dn = (__half2*)(sdn + r * KP + c4 * 4);
            dn[0] = q01; dn[1] = q23;
            int n = idx >> 3, c8 = idx & 7;
            *(int4*)(sW + n * KP + c8 * 8) = rw[it];
        }
    };

    loadChunk(0);

    for (int t = 0; t < NCHUNK; t++) {
        __syncthreads();   // previous chunk's MMA reads are done
        storeChunk();
        __syncthreads();   // tiles visible to all warps
        if (t + 1 < NCHUNK) loadChunk((t + 1) * KC);  // overlap gmem with MMA

#pragma unroll
        for (int kk = 0; kk < KC / 16; kk++) {
            const int kb = kk * 16;
            uint32_t A0, A1, A2, A3;
            uint32_t aaddr = a_base + (uint32_t)((a_row * KP + kb + a_kadd) * 2);
            LDSM4(A0, A1, A2, A3, aaddr);
#pragma unroll
            for (int g = 0; g < 8; g++) {
                const int n0 = g * 16;
                uint32_t B0, B1, B2, B3;
                uint32_t baddr = w_base + (uint32_t)(((n0 + b_nrow) * KP + kb + b_kadd) * 2);
                LDSM4(B0, B1, B2, B3, baddr);
                MMA16816(acc[2*g][0], acc[2*g][1], acc[2*g][2], acc[2*g][3],
                         A0, A1, A2, A3, B0, B1);
                MMA16816(acc[2*g+1][0], acc[2*g+1][1], acc[2*g+1][2], acc[2*g+1][3],
                         A0, A1, A2, A3, B2, B3);
            }
        }
    }

    // --- epilogue: per-row sum of squares of the 128-dim projected vector ---
    float slo = 0.f, shi = 0.f;
#pragma unroll
    for (int g = 0; g < 16; g++) {
        slo += acc[g][0] * acc[g][0] + acc[g][1] * acc[g][1];
        shi += acc[g][2] * acc[g][2] + acc[g][3] * acc[g][3];
    }
    // reduce across the 4 lanes that share each row (lane%4 partitions columns)
    slo += __shfl_xor_sync(0xffffffffu, slo, 1);
    slo += __shfl_xor_sync(0xffffffffu, slo, 2);
    shi += __shfl_xor_sync(0xffffffffu, shi, 1);
    shi += __shfl_xor_sync(0xffffffffu, shi, 2);

    if ((lane & 3) == 0) {
        int mat = warp >> 2;                 // 0 = dp, 1 = dn
        int r = m0 + (lane >> 2);
        sD[mat][r]     = slo;
        sD[mat][r + 8] = shi;
    }
    __syncthreads();

    if (tid < ROWS_CTA) {
        float loss = sD[0][tid] - sD[1][tid] + ALPHA_C;
        g_row_loss[row0 + tid] = loss > 0.f ? loss : 0.f;
    }
}

// ---------------------------------------------------------------------------
__global__ void reduce_kernel(float* __restrict__ out) {
    __shared__ float sm[8];
    int tid = threadIdx.x;
    float s = 0.f;
    for (int i = tid; i < BTOT; i += 256) s += g_row_loss[i];
#pragma unroll
    for (int o = 16; o > 0; o >>= 1) s += __shfl_xor_sync(0xffffffffu, s, o);
    if ((tid & 31) == 0) sm[tid >> 5] = s;
    __syncthreads();
    if (tid < 8) {
        s = sm[tid];
#pragma unroll
        for (int o = 4; o > 0; o >>= 1) s += __shfl_xor_sync(0x000000ffu, s, o);
        if (tid == 0) out[0] = s * (1.0f / (float)BTOT);
    }
}

// ---------------------------------------------------------------------------
extern "C" void kernel_launch(void* const* d_in, const int* in_sizes, int n_in,
                              void* d_out, int out_size) {
    const float* A  = (const float*)d_in[0];  // batch_anchor
    const float* P  = (const float*)d_in[1];  // batch_pos
    const float* Ng = (const float*)d_in[2];  // batch_neg
    const float* W  = (const float*)d_in[3];  // W  (b = d_in[4] cancels; unused)

    convW_kernel<<<(NDIM * KDIM + 255) / 256, 256>>>(W);
    triplet_main_kernel<<<BTOT / ROWS_CTA, 256>>>(A, P, Ng);
    reduce_kernel<<<1, 256>>>((float*)d_out);
}